// round 2
// baseline (speedup 1.0000x reference)
#include <cuda_runtime.h>
#include <math.h>

#define Pn   100000
#define Ln   20000
#define Tn   8
#define DEGn 48
#define Dn   64
#define NITERS 4

// ---------------- device scratch (no allocation allowed) ----------------
__device__ float g_path_state[Pn * Dn];            // 25.6 MB
__device__ float g_link_state[Ln * Dn];            // 5.1 MB
__device__ float g_pss[Pn * (Tn + 1) * Dn];        // 230 MB  [P][9][64]

__device__ float g_gru_wihT[64 * 192];
__device__ float g_gru_whhT[64 * 192];
__device__ float g_cell_wihT[64 * 192];
__device__ float g_cell_whhT[64 * 192];
__device__ float g_am_w1T[256 * 128];
__device__ float g_am_w2T[128 * 128];
__device__ float g_am_w3T[128 * 64];
__device__ float g_pe_w2T[64 * 64];
__device__ float g_le_w2T[64 * 64];

// ---------------- weight transposes (one small kernel) ----------------
__global__ void transpose_all_kernel(
    const float* __restrict__ gwih, const float* __restrict__ gwhh,
    const float* __restrict__ cwih, const float* __restrict__ cwhh,
    const float* __restrict__ w1,   const float* __restrict__ w2,
    const float* __restrict__ w3,   const float* __restrict__ pw2,
    const float* __restrict__ lw2)
{
    int i = blockIdx.x * blockDim.x + threadIdx.x;
    // [192,64] blocks: dst[c*192+r] = src[r*64+c]
    if (i < 12288) {
        int r = i >> 6, c = i & 63;
        g_gru_wihT[c * 192 + r] = gwih[i];
        g_gru_whhT[c * 192 + r] = gwhh[i];
        g_cell_wihT[c * 192 + r] = cwih[i];
        g_cell_whhT[c * 192 + r] = cwhh[i];
    }
    if (i < 32768) {               // am_w1 [128,256] -> [256][128]
        int r = i >> 8, c = i & 255;
        g_am_w1T[c * 128 + r] = w1[i];
    }
    if (i < 16384) {               // am_w2 [128,128]
        int r = i >> 7, c = i & 127;
        g_am_w2T[c * 128 + r] = w2[i];
    }
    if (i < 8192) {                // am_w3 [64,128] -> [128][64]
        int r = i >> 7, c = i & 127;
        g_am_w3T[c * 64 + r] = w3[i];
    }
    if (i < 4096) {                // pe_w2 / le_w2 [64,64]
        int r = i >> 6, c = i & 63;
        g_pe_w2T[c * 64 + r] = pw2[i];
        g_le_w2T[c * 64 + r] = lw2[i];
    }
}

// ---------------- encoders: relu(relu(x*w1 + b1) @ w2^T + b2) ----------------
__global__ __launch_bounds__(256) void encoder_kernel(
    const float* __restrict__ inp, const float* __restrict__ w1,
    const float* __restrict__ b1,  const float* __restrict__ b2,
    int N, int which)  // which: 0 = path, 1 = link
{
    __shared__ float h1[4][64];
    int g = threadIdx.x >> 6, d = threadIdx.x & 63;
    int p = blockIdx.x * 4 + g;
    float v = 0.f;
    if (p < N) {
        float x = inp[p];
        v = fmaxf(fmaf(x, w1[d], b1[d]), 0.f);
    }
    h1[g][d] = v;
    __syncthreads();
    if (p < N) {
        const float* w2T = which ? g_le_w2T : g_pe_w2T;
        float acc = b2[d];
#pragma unroll
        for (int k = 0; k < 64; k++)
            acc = fmaf(h1[g][k], w2T[k * 64 + d], acc);
        float* out = which ? g_link_state : g_path_state;
        out[p * 64 + d] = fmaxf(acc, 0.f);
    }
}

// ---------------- path GRU over T=8 steps ----------------
// 256 threads = 4 groups x 64 dims, 8 paths per group (32 paths/block).
__global__ __launch_bounds__(256) void gru_kernel(
    const int* __restrict__ l2p,          // [P*T]
    const float* __restrict__ bih, const float* __restrict__ bhh)
{
    __shared__ float x_sh[4][8][64];
    __shared__ float h_sh[4][8][64];
    int g = threadIdx.x >> 6, d = threadIdx.x & 63;
    int pbase = blockIdx.x * 32 + g * 8;

#pragma unroll
    for (int r = 0; r < 8; r++) {
        int p = pbase + r;
        float h0 = g_path_state[p * 64 + d];
        h_sh[g][r][d] = h0;
        g_pss[p * 576 + d] = h0;          // pss[:,0] = h0
    }
    float b0i = bih[d], b1i = bih[64 + d], b2i = bih[128 + d];
    float b0h = bhh[d], b1h = bhh[64 + d], b2h = bhh[128 + d];

    for (int t = 0; t < Tn; t++) {
        int li[8];
#pragma unroll
        for (int r = 0; r < 8; r++) {
            int p = pbase + r;
            int l = l2p[p * Tn + t];
            li[r] = l;
            x_sh[g][r][d] = (l >= 0) ? g_link_state[l * 64 + d] : 0.f;
        }
        __syncthreads();                   // x ready; prev h writes visible

        float gi0[8] = {0}, gi1[8] = {0}, gi2[8] = {0};
        float gh0[8] = {0}, gh1[8] = {0}, gh2[8] = {0};
        const float* wi = g_gru_wihT + d;
        const float* wh = g_gru_whhT + d;
#pragma unroll 4
        for (int k = 0; k < 64; k++) {
            float wi0 = wi[k * 192], wi1 = wi[k * 192 + 64], wi2 = wi[k * 192 + 128];
            float wh0 = wh[k * 192], wh1 = wh[k * 192 + 64], wh2 = wh[k * 192 + 128];
#pragma unroll
            for (int r = 0; r < 8; r++) {
                float xv = x_sh[g][r][k];
                float hv = h_sh[g][r][k];
                gi0[r] = fmaf(xv, wi0, gi0[r]);
                gi1[r] = fmaf(xv, wi1, gi1[r]);
                gi2[r] = fmaf(xv, wi2, gi2[r]);
                gh0[r] = fmaf(hv, wh0, gh0[r]);
                gh1[r] = fmaf(hv, wh1, gh1[r]);
                gh2[r] = fmaf(hv, wh2, gh2[r]);
            }
        }
        __syncthreads();                   // all reads of h_sh/x_sh done

#pragma unroll
        for (int r = 0; r < 8; r++) {
            float hold = h_sh[g][r][d];
            float rr = 1.f / (1.f + expf(-(gi0[r] + b0i + gh0[r] + b0h)));
            float zz = 1.f / (1.f + expf(-(gi1[r] + b1i + gh1[r] + b1h)));
            float nn = tanhf(gi2[r] + b2i + rr * (gh2[r] + b2h));
            float hn = (1.f - zz) * nn + zz * hold;
            bool valid = li[r] >= 0;
            h_sh[g][r][d] = valid ? hn : hold;
            g_pss[(pbase + r) * 576 + (t + 1) * 64 + d] = valid ? hn : 0.f;
        }
        // next iteration's leading __syncthreads() (after x writes) orders h updates
    }
    __syncthreads();
#pragma unroll
    for (int r = 0; r < 8; r++)
        g_path_state[(pbase + r) * 64 + d] = h_sh[g][r][d];
}

// ---------------- link aggregation + MLP + GRUCell; 1 block per link ----------------
__global__ __launch_bounds__(256) void link_kernel(
    const int* __restrict__ p2l,           // [L*DEG*2]
    const float* __restrict__ am_b1, const float* __restrict__ am_b2,
    const float* __restrict__ am_b3,
    const float* __restrict__ cbih, const float* __restrict__ cbhh)
{
    __shared__ float agg[256];
    __shared__ float red[4][3][64];
    __shared__ int   redc[4];
    __shared__ float h1[128], h2[128], pa[64], hrow[64];
    __shared__ float gis[192], ghs[192];

    int l = blockIdx.x;
    int q = threadIdx.x >> 6, d = threadIdx.x & 63;

    float mn = INFINITY, mx = -INFINITY, sm = 0.f;
    int cnt = 0;
    for (int e = q; e < DEGn; e += 4) {
        int pi  = p2l[(l * DEGn + e) * 2];
        int pos = p2l[(l * DEGn + e) * 2 + 1];
        if (pi >= 0) {
            float v = g_pss[pi * 576 + pos * 64 + d];
            mn = fminf(mn, v); mx = fmaxf(mx, v); sm += v; cnt++;
        }
    }
    red[q][0][d] = mn; red[q][1][d] = mx; red[q][2][d] = sm;
    if (d == 0) redc[q] = cnt;
    __syncthreads();

    if (threadIdx.x < 64) {
        float amn = red[0][0][d], amx = red[0][1][d], s = red[0][2][d];
#pragma unroll
        for (int q2 = 1; q2 < 4; q2++) {
            amn = fminf(amn, red[q2][0][d]);
            amx = fmaxf(amx, red[q2][1][d]);
            s += red[q2][2][d];
        }
        int c = redc[0] + redc[1] + redc[2] + redc[3];
        float fc = (float)(c < 1 ? 1 : c);
        agg[d] = amn; agg[64 + d] = amx; agg[128 + d] = s; agg[192 + d] = s / fc;
        hrow[d] = g_link_state[l * 64 + d];
    }
    __syncthreads();

    if (threadIdx.x < 128) {
        int j = threadIdx.x;
        float acc = am_b1[j];
#pragma unroll 8
        for (int k = 0; k < 256; k++)
            acc = fmaf(agg[k], g_am_w1T[k * 128 + j], acc);
        h1[j] = fmaxf(acc, 0.f);
    }
    __syncthreads();
    if (threadIdx.x < 128) {
        int j = threadIdx.x;
        float acc = am_b2[j];
#pragma unroll 8
        for (int k = 0; k < 128; k++)
            acc = fmaf(h1[k], g_am_w2T[k * 128 + j], acc);
        h2[j] = fmaxf(acc, 0.f);
    }
    __syncthreads();
    if (threadIdx.x < 64) {
        int j = threadIdx.x;
        float acc = am_b3[j];
#pragma unroll 8
        for (int k = 0; k < 128; k++)
            acc = fmaf(h2[k], g_am_w3T[k * 64 + j], acc);
        pa[j] = fmaxf(acc, 0.f);
    }
    __syncthreads();
    if (threadIdx.x < 192) {
        int j = threadIdx.x;
        float ai = cbih[j], ah = cbhh[j];
#pragma unroll 8
        for (int k = 0; k < 64; k++) {
            ai = fmaf(pa[k],   g_cell_wihT[k * 192 + j], ai);
            ah = fmaf(hrow[k], g_cell_whhT[k * 192 + j], ah);
        }
        gis[j] = ai; ghs[j] = ah;
    }
    __syncthreads();
    if (threadIdx.x < 64) {
        float hold = hrow[d];
        float rr = 1.f / (1.f + expf(-(gis[d] + ghs[d])));
        float zz = 1.f / (1.f + expf(-(gis[64 + d] + ghs[64 + d])));
        float nn = tanhf(gis[128 + d] + rr * ghs[128 + d]);
        g_link_state[l * 64 + d] = (1.f - zz) * nn + zz * hold;
    }
}

// ---------------- output copy: (path_state, link_state) concatenated ----------------
__global__ void copyout_kernel(float* __restrict__ out, int out_size)
{
    int i = blockIdx.x * blockDim.x + threadIdx.x;
    if (i >= out_size) return;
    if (i < Pn * Dn)
        out[i] = g_path_state[i];
    else if (i < Pn * Dn + Ln * Dn)
        out[i] = g_link_state[i - Pn * Dn];
}

// ---------------- launch ----------------
extern "C" void kernel_launch(void* const* d_in, const int* in_sizes, int n_in,
                              void* d_out, int out_size)
{
    const float* traffic  = (const float*)d_in[0];
    const float* capacity = (const float*)d_in[1];
    const int*   l2p      = (const int*)d_in[2];
    const int*   p2l      = (const int*)d_in[3];
    const float* pe_w1 = (const float*)d_in[4];
    const float* pe_b1 = (const float*)d_in[5];
    const float* pe_w2 = (const float*)d_in[6];
    const float* pe_b2 = (const float*)d_in[7];
    const float* le_w1 = (const float*)d_in[8];
    const float* le_b1 = (const float*)d_in[9];
    const float* le_w2 = (const float*)d_in[10];
    const float* le_b2 = (const float*)d_in[11];
    const float* gru_wih = (const float*)d_in[12];
    const float* gru_whh = (const float*)d_in[13];
    const float* gru_bih = (const float*)d_in[14];
    const float* gru_bhh = (const float*)d_in[15];
    const float* cell_wih = (const float*)d_in[16];
    const float* cell_whh = (const float*)d_in[17];
    const float* cell_bih = (const float*)d_in[18];
    const float* cell_bhh = (const float*)d_in[19];
    const float* am_w1 = (const float*)d_in[20];
    const float* am_b1 = (const float*)d_in[21];
    const float* am_w2 = (const float*)d_in[22];
    const float* am_b2 = (const float*)d_in[23];
    const float* am_w3 = (const float*)d_in[24];
    const float* am_b3 = (const float*)d_in[25];

    transpose_all_kernel<<<(32768 + 255) / 256, 256>>>(
        gru_wih, gru_whh, cell_wih, cell_whh, am_w1, am_w2, am_w3, pe_w2, le_w2);

    encoder_kernel<<<(Pn + 3) / 4, 256>>>(traffic, pe_w1, pe_b1, pe_b2, Pn, 0);
    encoder_kernel<<<(Ln + 3) / 4, 256>>>(capacity, le_w1, le_b1, le_b2, Ln, 1);

    for (int it = 0; it < NITERS; it++) {
        gru_kernel<<<Pn / 32, 256>>>(l2p, gru_bih, gru_bhh);
        link_kernel<<<Ln, 256>>>(p2l, am_b1, am_b2, am_b3, cell_bih, cell_bhh);
    }

    copyout_kernel<<<(out_size + 255) / 256, 256>>>((float*)d_out, out_size);
}

// round 6
// speedup vs baseline: 1.2994x; 1.2994x over previous
#include <cuda_runtime.h>
#include <math.h>

#define Pn   100000
#define Ln   20000
#define Tn   8
#define DEGn 48
#define Dn   64
#define NITERS 4

typedef unsigned long long ull;

// ---------------- device scratch (no allocation allowed) ----------------
__device__ float g_path_state[Pn * Dn];            // 25.6 MB
__device__ float g_link_state[Ln * Dn];            // 5.1 MB
__device__ float g_pss[Pn * (Tn + 1) * Dn];        // 230 MB  [P][9][64]
__device__ float g_Y[Ln * 192];                    // 15.4 MB: link gi precompute

__device__ float g_gru_wihT[64 * 192];             // [k][j]
__device__ __align__(16) float g_whh_p[32 * 384];  // k-pair packed: (kp,j) -> [kp*384 + j*2 + (k&1)]
__device__ float g_cell_wihT[64 * 192];
__device__ float g_cell_whhT[64 * 192];
__device__ float g_am_w1T[256 * 128];
__device__ float g_am_w2T[128 * 128];
__device__ float g_am_w3T[128 * 64];
__device__ float g_pe_w2T[64 * 64];
__device__ float g_le_w2T[64 * 64];

// ---------------- helpers ----------------
__device__ __forceinline__ void ffma2(ull& d, ull a, ull b) {
    asm("fma.rn.f32x2 %0, %1, %2, %0;" : "+l"(d) : "l"(a), "l"(b));
}
__device__ __forceinline__ float hsum2(ull v) {
    float lo, hi;
    asm("mov.b64 {%0,%1}, %2;" : "=f"(lo), "=f"(hi) : "l"(v));
    return lo + hi;
}
__device__ __forceinline__ float sigf(float x) {
    return __fdividef(1.f, 1.f + __expf(-x));
}
__device__ __forceinline__ float tanhfast(float x) {
    return __fdividef(2.f, 1.f + __expf(-2.f * x)) - 1.f;
}

// ---------------- weight transposes (one small kernel) ----------------
__global__ void transpose_all_kernel(
    const float* __restrict__ gwih, const float* __restrict__ gwhh,
    const float* __restrict__ cwih, const float* __restrict__ cwhh,
    const float* __restrict__ w1,   const float* __restrict__ w2,
    const float* __restrict__ w3,   const float* __restrict__ pw2,
    const float* __restrict__ lw2)
{
    int i = blockIdx.x * blockDim.x + threadIdx.x;
    if (i < 12288) {                // [192,64] sources; r = gate-row j, c = k
        int r = i >> 6, c = i & 63;
        g_gru_wihT[c * 192 + r] = gwih[i];
        // k-pair packed Whh: element (k=c, j=r)
        g_whh_p[(c >> 1) * 384 + r * 2 + (c & 1)] = gwhh[i];
        g_cell_wihT[c * 192 + r] = cwih[i];
        g_cell_whhT[c * 192 + r] = cwhh[i];
    }
    if (i < 32768) {                // am_w1 [128,256] -> [256][128]
        int r = i >> 8, c = i & 255;
        g_am_w1T[c * 128 + r] = w1[i];
    }
    if (i < 16384) {                // am_w2 [128,128]
        int r = i >> 7, c = i & 127;
        g_am_w2T[c * 128 + r] = w2[i];
    }
    if (i < 8192) {                 // am_w3 [64,128] -> [128][64]
        int r = i >> 7, c = i & 127;
        g_am_w3T[c * 64 + r] = w3[i];
    }
    if (i < 4096) {                 // pe_w2 / le_w2 [64,64]
        int r = i >> 6, c = i & 63;
        g_pe_w2T[c * 64 + r] = pw2[i];
        g_le_w2T[c * 64 + r] = lw2[i];
    }
}

// ---------------- encoders: relu(relu(x*w1 + b1) @ w2^T + b2) ----------------
__global__ __launch_bounds__(256) void encoder_kernel(
    const float* __restrict__ inp, const float* __restrict__ w1,
    const float* __restrict__ b1,  const float* __restrict__ b2,
    int N, int which)
{
    __shared__ float h1[4][64];
    int g = threadIdx.x >> 6, d = threadIdx.x & 63;
    int p = blockIdx.x * 4 + g;
    float v = 0.f;
    if (p < N) {
        float x = inp[p];
        v = fmaxf(fmaf(x, w1[d], b1[d]), 0.f);
    }
    h1[g][d] = v;
    __syncthreads();
    if (p < N) {
        const float* w2T = which ? g_le_w2T : g_pe_w2T;
        float acc = b2[d];
#pragma unroll
        for (int k = 0; k < 64; k++)
            acc = fmaf(h1[g][k], w2T[k * 64 + d], acc);
        float* out = which ? g_link_state : g_path_state;
        out[p * 64 + d] = fmaxf(acc, 0.f);
    }
}

// ---------------- per-iteration link gi precompute: Y = ls @ Wih^T + bih ----------------
__global__ __launch_bounds__(192) void linkgi_kernel(const float* __restrict__ bih)
{
    __shared__ float ls[64];
    int l = blockIdx.x;
    int j = threadIdx.x;
    if (j < 64) ls[j] = g_link_state[l * 64 + j];
    __syncthreads();
    float acc = __ldg(&bih[j]);
#pragma unroll 8
    for (int k = 0; k < 64; k++)
        acc = fmaf(ls[k], g_gru_wihT[k * 192 + j], acc);
    g_Y[l * 192 + j] = acc;
}

// ---------------- path GRU over T=8 steps ----------------
// 256 threads = 4 groups x 64 dims, 8 paths/group. gh via FFMA2 k-pair packing;
// gi gathered from precomputed Y (bih already baked in).
__global__ __launch_bounds__(256) void gru_kernel(
    const int* __restrict__ l2p, const float* __restrict__ bhh)
{
    __shared__ float2 h_sh2[4][8][32];
    int g = threadIdx.x >> 6, d = threadIdx.x & 63;
    int pbase = blockIdx.x * 32 + g * 8;

#pragma unroll
    for (int r = 0; r < 8; r++) {
        int p = pbase + r;
        float h0 = g_path_state[p * 64 + d];
        ((float*)&h_sh2[g][r][0])[d] = h0;
        g_pss[p * 576 + d] = h0;
    }
    float b0h = __ldg(&bhh[d]);
    float b1h = __ldg(&bhh[64 + d]);
    float b2h = __ldg(&bhh[128 + d]);
    __syncthreads();

    const ull* wq = reinterpret_cast<const ull*>(g_whh_p);   // (kp,j) at [kp*192 + j]

    for (int t = 0; t < Tn; t++) {
        int li[8];
        float gi0[8], gi1[8], gi2[8];
#pragma unroll
        for (int r = 0; r < 8; r++) {
            int l = __ldg(&l2p[(pbase + r) * Tn + t]);
            li[r] = l;
            int lc = l < 0 ? 0 : l;
            const float* yr = g_Y + lc * 192 + d;
            gi0[r] = yr[0];
            gi1[r] = yr[64];
            gi2[r] = yr[128];
        }

        ull a0[8], a1[8], a2[8];
#pragma unroll
        for (int r = 0; r < 8; r++) { a0[r] = 0ull; a1[r] = 0ull; a2[r] = 0ull; }

#pragma unroll 4
        for (int kp = 0; kp < 32; kp++) {
            ull w0 = __ldg(&wq[kp * 192 + d]);
            ull w1 = __ldg(&wq[kp * 192 + 64 + d]);
            ull w2 = __ldg(&wq[kp * 192 + 128 + d]);
#pragma unroll
            for (int r = 0; r < 8; r++) {
                ull hp = reinterpret_cast<const ull*>(&h_sh2[g][r][0])[kp];
                ffma2(a0[r], hp, w0);
                ffma2(a1[r], hp, w1);
                ffma2(a2[r], hp, w2);
            }
        }
        __syncthreads();   // all h reads done before updates

#pragma unroll
        for (int r = 0; r < 8; r++) {
            float hold = ((float*)&h_sh2[g][r][0])[d];
            float gh0 = hsum2(a0[r]) + b0h;
            float gh1 = hsum2(a1[r]) + b1h;
            float gh2 = hsum2(a2[r]) + b2h;
            float rr = sigf(gi0[r] + gh0);
            float zz = sigf(gi1[r] + gh1);
            float nn = tanhfast(gi2[r] + rr * gh2);
            float hn = fmaf(zz, hold - nn, nn);    // (1-z)n + z*h
            bool valid = li[r] >= 0;
            ((float*)&h_sh2[g][r][0])[d] = valid ? hn : hold;
            g_pss[(pbase + r) * 576 + (t + 1) * 64 + d] = valid ? hn : 0.f;
        }
        __syncthreads();   // updates visible before next t's matmul
    }

#pragma unroll
    for (int r = 0; r < 8; r++)
        g_path_state[(pbase + r) * 64 + d] = ((float*)&h_sh2[g][r][0])[d];
}

// ---------------- link aggregation + MLP + GRUCell; 1 block per link ----------------
__global__ __launch_bounds__(256) void link_kernel(
    const int* __restrict__ p2l,
    const float* __restrict__ am_b1, const float* __restrict__ am_b2,
    const float* __restrict__ am_b3,
    const float* __restrict__ cbih, const float* __restrict__ cbhh)
{
    __shared__ float agg[256];
    __shared__ float red[4][3][64];
    __shared__ int   redc[4];
    __shared__ float h1[128], h2[128], pa[64], hrow[64];
    __shared__ float gis[192], ghs[192];

    int l = blockIdx.x;
    int q = threadIdx.x >> 6, d = threadIdx.x & 63;

    float mn = INFINITY, mx = -INFINITY, sm = 0.f;
    int cnt = 0;
    for (int e = q; e < DEGn; e += 4) {
        int pi  = __ldg(&p2l[(l * DEGn + e) * 2]);
        int pos = __ldg(&p2l[(l * DEGn + e) * 2 + 1]);
        if (pi >= 0) {
            float v = g_pss[pi * 576 + pos * 64 + d];
            mn = fminf(mn, v); mx = fmaxf(mx, v); sm += v; cnt++;
        }
    }
    red[q][0][d] = mn; red[q][1][d] = mx; red[q][2][d] = sm;
    if (d == 0) redc[q] = cnt;
    __syncthreads();

    if (threadIdx.x < 64) {
        float amn = red[0][0][d], amx = red[0][1][d], s = red[0][2][d];
#pragma unroll
        for (int q2 = 1; q2 < 4; q2++) {
            amn = fminf(amn, red[q2][0][d]);
            amx = fmaxf(amx, red[q2][1][d]);
            s += red[q2][2][d];
        }
        int c = redc[0] + redc[1] + redc[2] + redc[3];
        float fc = (float)(c < 1 ? 1 : c);
        agg[d] = amn; agg[64 + d] = amx; agg[128 + d] = s; agg[192 + d] = __fdividef(s, fc);
        hrow[d] = g_link_state[l * 64 + d];
    }
    __syncthreads();

    if (threadIdx.x < 128) {
        int j = threadIdx.x;
        float acc = __ldg(&am_b1[j]);
#pragma unroll 8
        for (int k = 0; k < 256; k++)
            acc = fmaf(agg[k], g_am_w1T[k * 128 + j], acc);
        h1[j] = fmaxf(acc, 0.f);
    }
    __syncthreads();
    if (threadIdx.x < 128) {
        int j = threadIdx.x;
        float acc = __ldg(&am_b2[j]);
#pragma unroll 8
        for (int k = 0; k < 128; k++)
            acc = fmaf(h1[k], g_am_w2T[k * 128 + j], acc);
        h2[j] = fmaxf(acc, 0.f);
    }
    __syncthreads();
    if (threadIdx.x < 64) {
        int j = threadIdx.x;
        float acc = __ldg(&am_b3[j]);
#pragma unroll 8
        for (int k = 0; k < 128; k++)
            acc = fmaf(h2[k], g_am_w3T[k * 64 + j], acc);
        pa[j] = fmaxf(acc, 0.f);
    }
    __syncthreads();
    if (threadIdx.x < 192) {
        int j = threadIdx.x;
        float ai = __ldg(&cbih[j]), ah = __ldg(&cbhh[j]);
#pragma unroll 8
        for (int k = 0; k < 64; k++) {
            ai = fmaf(pa[k],   g_cell_wihT[k * 192 + j], ai);
            ah = fmaf(hrow[k], g_cell_whhT[k * 192 + j], ah);
        }
        gis[j] = ai; ghs[j] = ah;
    }
    __syncthreads();
    if (threadIdx.x < 64) {
        float hold = hrow[d];
        float rr = sigf(gis[d] + ghs[d]);
        float zz = sigf(gis[64 + d] + ghs[64 + d]);
        float nn = tanhfast(gis[128 + d] + rr * ghs[128 + d]);
        g_link_state[l * 64 + d] = fmaf(zz, hold - nn, nn);
    }
}

// ---------------- output copy ----------------
__global__ void copyout_kernel(float* __restrict__ out, int out_size)
{
    int i = blockIdx.x * blockDim.x + threadIdx.x;
    if (i >= out_size) return;
    if (i < Pn * Dn)
        out[i] = g_path_state[i];
    else if (i < Pn * Dn + Ln * Dn)
        out[i] = g_link_state[i - Pn * Dn];
}

// ---------------- launch ----------------
extern "C" void kernel_launch(void* const* d_in, const int* in_sizes, int n_in,
                              void* d_out, int out_size)
{
    const float* traffic  = (const float*)d_in[0];
    const float* capacity = (const float*)d_in[1];
    const int*   l2p      = (const int*)d_in[2];
    const int*   p2l      = (const int*)d_in[3];
    const float* pe_w1 = (const float*)d_in[4];
    const float* pe_b1 = (const float*)d_in[5];
    const float* pe_w2 = (const float*)d_in[6];
    const float* pe_b2 = (const float*)d_in[7];
    const float* le_w1 = (const float*)d_in[8];
    const float* le_b1 = (const float*)d_in[9];
    const float* le_w2 = (const float*)d_in[10];
    const float* le_b2 = (const float*)d_in[11];
    const float* gru_wih = (const float*)d_in[12];
    const float* gru_whh = (const float*)d_in[13];
    const float* gru_bih = (const float*)d_in[14];
    const float* gru_bhh = (const float*)d_in[15];
    const float* cell_wih = (const float*)d_in[16];
    const float* cell_whh = (const float*)d_in[17];
    const float* cell_bih = (const float*)d_in[18];
    const float* cell_bhh = (const float*)d_in[19];
    const float* am_w1 = (const float*)d_in[20];
    const float* am_b1 = (const float*)d_in[21];
    const float* am_w2 = (const float*)d_in[22];
    const float* am_b2 = (const float*)d_in[23];
    const float* am_w3 = (const float*)d_in[24];
    const float* am_b3 = (const float*)d_in[25];

    transpose_all_kernel<<<(32768 + 255) / 256, 256>>>(
        gru_wih, gru_whh, cell_wih, cell_whh, am_w1, am_w2, am_w3, pe_w2, le_w2);

    encoder_kernel<<<(Pn + 3) / 4, 256>>>(traffic, pe_w1, pe_b1, pe_b2, Pn, 0);
    encoder_kernel<<<(Ln + 3) / 4, 256>>>(capacity, le_w1, le_b1, le_b2, Ln, 1);

    for (int it = 0; it < NITERS; it++) {
        linkgi_kernel<<<Ln, 192>>>(gru_bih);
        gru_kernel<<<Pn / 32, 256>>>(l2p, gru_bhh);
        link_kernel<<<Ln, 256>>>(p2l, am_b1, am_b2, am_b3, cell_bih, cell_bhh);
    }

    copyout_kernel<<<(out_size + 255) / 256, 256>>>((float*)d_out, out_size);
}

// round 8
// speedup vs baseline: 1.3689x; 1.0535x over previous
#include <cuda_runtime.h>
#include <math.h>

#define Pn   100000
#define Ln   20000
#define Tn   8
#define DEGn 48
#define Dn   64
#define NITERS 4

typedef unsigned long long ull;

// ---------------- device scratch (no allocation allowed) ----------------
__device__ float g_path_state[Pn * Dn];            // 25.6 MB
__device__ float g_link_state[Ln * Dn];            // 5.1 MB
__device__ float g_pss[Pn * (Tn + 1) * Dn];        // 230 MB  [P][9][64]
__device__ float g_Y[Ln * 192];                    // 15.4 MB: link gi precompute

__device__ float g_gru_wihT[64 * 192];                 // scalar [k][j] (linkgi only)
__device__ __align__(16) float g_wih_p [32 * 384];     // k-pair packed gru Wih
__device__ __align__(16) float g_whh_p [32 * 384];     // k-pair packed gru Whh
__device__ __align__(16) float g_cwih_p[32 * 384];     // k-pair packed cell Wih
__device__ __align__(16) float g_cwhh_p[32 * 384];     // k-pair packed cell Whh
__device__ __align__(16) float g_am_w1p[128 * 256];    // kp*256 + j*2 + par, kp<128, j<128
__device__ __align__(16) float g_am_w2p[64 * 256];     // kp*256 + j*2 + par, kp<64,  j<128
__device__ __align__(16) float g_am_w3p[64 * 128];     // kp*128 + j*2 + par, kp<64,  j<64
__device__ float g_pe_w2T[64 * 64];
__device__ float g_le_w2T[64 * 64];

// ---------------- helpers ----------------
__device__ __forceinline__ void ffma2(ull& d, ull a, ull b) {
    asm("fma.rn.f32x2 %0, %1, %2, %0;" : "+l"(d) : "l"(a), "l"(b));
}
__device__ __forceinline__ float hsum2(ull v) {
    float lo, hi;
    asm("mov.b64 {%0,%1}, %2;" : "=f"(lo), "=f"(hi) : "l"(v));
    return lo + hi;
}
__device__ __forceinline__ float sigf(float x) {
    return __fdividef(1.f, 1.f + __expf(-x));
}
__device__ __forceinline__ float tanhfast(float x) {
    return __fdividef(2.f, 1.f + __expf(-2.f * x)) - 1.f;
}

// ---------------- weight transposes / pair packing (one small kernel) ----------------
__global__ void transpose_all_kernel(
    const float* __restrict__ gwih, const float* __restrict__ gwhh,
    const float* __restrict__ cwih, const float* __restrict__ cwhh,
    const float* __restrict__ w1,   const float* __restrict__ w2,
    const float* __restrict__ w3,   const float* __restrict__ pw2,
    const float* __restrict__ lw2)
{
    int i = blockIdx.x * blockDim.x + threadIdx.x;
    if (i < 12288) {                // [192,64] sources; r = gate-row j, c = k
        int r = i >> 6, c = i & 63;
        int pk = (c >> 1) * 384 + r * 2 + (c & 1);
        g_gru_wihT[c * 192 + r] = gwih[i];
        g_wih_p [pk] = gwih[i];
        g_whh_p [pk] = gwhh[i];
        g_cwih_p[pk] = cwih[i];
        g_cwhh_p[pk] = cwhh[i];
    }
    if (i < 32768) {                // am_w1 [128,256]
        int r = i >> 8, c = i & 255;
        g_am_w1p[(c >> 1) * 256 + r * 2 + (c & 1)] = w1[i];
    }
    if (i < 16384) {                // am_w2 [128,128]
        int r = i >> 7, c = i & 127;
        g_am_w2p[(c >> 1) * 256 + r * 2 + (c & 1)] = w2[i];
    }
    if (i < 8192) {                 // am_w3 [64,128]
        int r = i >> 7, c = i & 127;
        g_am_w3p[(c >> 1) * 128 + r * 2 + (c & 1)] = w3[i];
    }
    if (i < 4096) {                 // pe_w2 / le_w2 [64,64]
        int r = i >> 6, c = i & 63;
        g_pe_w2T[c * 64 + r] = pw2[i];
        g_le_w2T[c * 64 + r] = lw2[i];
    }
}

// ---------------- encoders: relu(relu(x*w1 + b1) @ w2^T + b2) ----------------
__global__ __launch_bounds__(256) void encoder_kernel(
    const float* __restrict__ inp, const float* __restrict__ w1,
    const float* __restrict__ b1,  const float* __restrict__ b2,
    int N, int which)
{
    __shared__ float h1[4][64];
    int g = threadIdx.x >> 6, d = threadIdx.x & 63;
    int p = blockIdx.x * 4 + g;
    float v = 0.f;
    if (p < N) {
        float x = inp[p];
        v = fmaxf(fmaf(x, w1[d], b1[d]), 0.f);
    }
    h1[g][d] = v;
    __syncthreads();
    if (p < N) {
        const float* w2T = which ? g_le_w2T : g_pe_w2T;
        float acc = b2[d];
#pragma unroll
        for (int k = 0; k < 64; k++)
            acc = fmaf(h1[g][k], w2T[k * 64 + d], acc);
        float* out = which ? g_link_state : g_path_state;
        out[p * 64 + d] = fmaxf(acc, 0.f);
    }
}

// ---------------- Y = ls @ Wih^T + bih (iteration 0 only; later iters fused) ----------------
__global__ __launch_bounds__(192) void linkgi_kernel(const float* __restrict__ bih)
{
    __shared__ float ls[64];
    int l = blockIdx.x;
    int j = threadIdx.x;
    if (j < 64) ls[j] = g_link_state[l * 64 + j];
    __syncthreads();
    float acc = __ldg(&bih[j]);
#pragma unroll 8
    for (int k = 0; k < 64; k++)
        acc = fmaf(ls[k], g_gru_wihT[k * 192 + j], acc);
    g_Y[l * 192 + j] = acc;
}

// ---------------- path GRU over T=8 steps ----------------
// 256 threads = 4 groups x 64 dims, 8 paths/group. gh via FFMA2 k-pair packing;
// gi gathered from precomputed Y in the epilogue (low reg pressure in hot loop).
__global__ __launch_bounds__(256, 3) void gru_kernel(
    const int* __restrict__ l2p, const float* __restrict__ bhh)
{
    __shared__ float2 h_sh2[4][8][32];
    int g = threadIdx.x >> 6, d = threadIdx.x & 63;
    int pbase = blockIdx.x * 32 + g * 8;

#pragma unroll
    for (int r = 0; r < 8; r++) {
        int p = pbase + r;
        float h0 = g_path_state[p * 64 + d];
        ((float*)&h_sh2[g][r][0])[d] = h0;
        g_pss[p * 576 + d] = h0;
    }
    float b0h = __ldg(&bhh[d]);
    float b1h = __ldg(&bhh[64 + d]);
    float b2h = __ldg(&bhh[128 + d]);
    __syncthreads();

    const ull* wq = reinterpret_cast<const ull*>(g_whh_p);   // (kp,j) at [kp*192 + j]

    for (int t = 0; t < Tn; t++) {
        ull a0[8], a1[8], a2[8];
#pragma unroll
        for (int r = 0; r < 8; r++) { a0[r] = 0ull; a1[r] = 0ull; a2[r] = 0ull; }

#pragma unroll 4
        for (int kp = 0; kp < 32; kp++) {
            ull w0 = __ldg(&wq[kp * 192 + d]);
            ull w1 = __ldg(&wq[kp * 192 + 64 + d]);
            ull w2 = __ldg(&wq[kp * 192 + 128 + d]);
#pragma unroll
            for (int r = 0; r < 8; r++) {
                ull hp = reinterpret_cast<const ull*>(&h_sh2[g][r][0])[kp];
                ffma2(a0[r], hp, w0);
                ffma2(a1[r], hp, w1);
                ffma2(a2[r], hp, w2);
            }
        }
        __syncthreads();   // all h reads done before updates

        int lk[8];
#pragma unroll
        for (int r = 0; r < 8; r++)
            lk[r] = __ldg(&l2p[(pbase + r) * Tn + t]);

#pragma unroll
        for (int r = 0; r < 8; r++) {
            int lc = lk[r] < 0 ? 0 : lk[r];
            const float* yr = g_Y + lc * 192 + d;
            float gi0 = yr[0], gi1 = yr[64], gi2 = yr[128];
            float hold = ((float*)&h_sh2[g][r][0])[d];
            float gh0 = hsum2(a0[r]) + b0h;
            float gh1 = hsum2(a1[r]) + b1h;
            float gh2 = hsum2(a2[r]) + b2h;
            float rr = sigf(gi0 + gh0);
            float zz = sigf(gi1 + gh1);
            float nn = tanhfast(gi2 + rr * gh2);
            float hn = fmaf(zz, hold - nn, nn);    // (1-z)n + z*h
            bool valid = lk[r] >= 0;
            ((float*)&h_sh2[g][r][0])[d] = valid ? hn : hold;
            g_pss[(pbase + r) * 576 + (t + 1) * 64 + d] = valid ? hn : 0.f;
        }
        __syncthreads();   // updates visible before next t's matmul
    }

#pragma unroll
    for (int r = 0; r < 8; r++)
        g_path_state[(pbase + r) * 64 + d] = ((float*)&h_sh2[g][r][0])[d];
}

// ---------------- link: gather + MLP + GRUCell + fused next-iter Y; 1 block/link ----------------
__global__ __launch_bounds__(256) void link_kernel(
    const int2* __restrict__ p2l2,
    const float* __restrict__ am_b1, const float* __restrict__ am_b2,
    const float* __restrict__ am_b3,
    const float* __restrict__ cbih, const float* __restrict__ cbhh,
    const float* __restrict__ gbih)
{
    __shared__ __align__(8) float agg[256];
    __shared__ float red[4][3][64];
    __shared__ int   redc[4];
    __shared__ __align__(8) float h1[128];
    __shared__ __align__(8) float h2[128];
    __shared__ __align__(8) float pa[64];
    __shared__ __align__(8) float hrow[64];
    __shared__ __align__(8) float lnew[64];
    __shared__ float part[2][128];
    __shared__ float part4[4][64];
    __shared__ float gis[192], ghs[192];

    int l = blockIdx.x;
    int tid = threadIdx.x;
    int q = tid >> 6, d = tid & 63;
    int hf = tid >> 7, j = tid & 127;

    if (tid < 64) hrow[tid] = g_link_state[l * 64 + tid];

    // ---- gather + min/max/sum over DEG ----
    float mn = INFINITY, mx = -INFINITY, sm = 0.f;
    int cnt = 0;
#pragma unroll
    for (int e = q; e < DEGn; e += 4) {
        int2 pp = __ldg(&p2l2[l * DEGn + e]);
        if (pp.x >= 0) {
            float v = g_pss[pp.x * 576 + pp.y * 64 + d];
            mn = fminf(mn, v); mx = fmaxf(mx, v); sm += v; cnt++;
        }
    }
    red[q][0][d] = mn; red[q][1][d] = mx; red[q][2][d] = sm;
    if (d == 0) redc[q] = cnt;
    __syncthreads();

    if (tid < 64) {
        float amn = red[0][0][d], amx = red[0][1][d], s = red[0][2][d];
#pragma unroll
        for (int q2 = 1; q2 < 4; q2++) {
            amn = fminf(amn, red[q2][0][d]);
            amx = fmaxf(amx, red[q2][1][d]);
            s += red[q2][2][d];
        }
        int c = redc[0] + redc[1] + redc[2] + redc[3];
        float fc = (float)(c < 1 ? 1 : c);
        agg[d] = amn; agg[64 + d] = amx; agg[128 + d] = s; agg[192 + d] = __fdividef(s, fc);
    }
    __syncthreads();

    // ---- MLP layer 1: [256] -> [128], k split in 2 halves ----
    {
        const ull* aggq = reinterpret_cast<const ull*>(agg);
        const ull* wq = reinterpret_cast<const ull*>(g_am_w1p);
        ull acc = 0ull;
#pragma unroll 8
        for (int kp = hf * 64; kp < hf * 64 + 64; kp++)
            ffma2(acc, aggq[kp], wq[kp * 128 + j]);
        part[hf][j] = hsum2(acc);
    }
    __syncthreads();
    if (tid < 128)
        h1[tid] = fmaxf(part[0][tid] + part[1][tid] + __ldg(&am_b1[tid]), 0.f);
    __syncthreads();

    // ---- MLP layer 2: [128] -> [128] ----
    {
        const ull* h1q = reinterpret_cast<const ull*>(h1);
        const ull* wq = reinterpret_cast<const ull*>(g_am_w2p);
        ull acc = 0ull;
#pragma unroll 8
        for (int kp = hf * 32; kp < hf * 32 + 32; kp++)
            ffma2(acc, h1q[kp], wq[kp * 128 + j]);
        part[hf][j] = hsum2(acc);
    }
    __syncthreads();
    if (tid < 128)
        h2[tid] = fmaxf(part[0][tid] + part[1][tid] + __ldg(&am_b2[tid]), 0.f);
    __syncthreads();

    // ---- MLP layer 3: [128] -> [64], k split in 4 quarters ----
    {
        const ull* h2q = reinterpret_cast<const ull*>(h2);
        const ull* wq = reinterpret_cast<const ull*>(g_am_w3p);
        ull acc = 0ull;
#pragma unroll 8
        for (int kp = q * 16; kp < q * 16 + 16; kp++)
            ffma2(acc, h2q[kp], wq[kp * 64 + d]);
        part4[q][d] = hsum2(acc);
    }
    __syncthreads();
    if (tid < 64)
        pa[tid] = fmaxf(part4[0][tid] + part4[1][tid] + part4[2][tid] + part4[3][tid]
                        + __ldg(&am_b3[tid]), 0.f);
    __syncthreads();

    // ---- GRUCell gates ----
    if (tid < 192) {
        const ull* paq = reinterpret_cast<const ull*>(pa);
        const ull* hq  = reinterpret_cast<const ull*>(hrow);
        const ull* wiq = reinterpret_cast<const ull*>(g_cwih_p);
        const ull* whq = reinterpret_cast<const ull*>(g_cwhh_p);
        ull ai = 0ull, ah = 0ull;
#pragma unroll 8
        for (int kp = 0; kp < 32; kp++) {
            ffma2(ai, paq[kp], wiq[kp * 192 + tid]);
            ffma2(ah, hq[kp],  whq[kp * 192 + tid]);
        }
        gis[tid] = hsum2(ai) + __ldg(&cbih[tid]);
        ghs[tid] = hsum2(ah) + __ldg(&cbhh[tid]);
    }
    __syncthreads();
    if (tid < 64) {
        float hold = hrow[tid];
        float rr = sigf(gis[tid] + ghs[tid]);
        float zz = sigf(gis[64 + tid] + ghs[64 + tid]);
        float nn = tanhfast(gis[128 + tid] + rr * ghs[128 + tid]);
        float hn = fmaf(zz, hold - nn, nn);
        lnew[tid] = hn;
        g_link_state[l * 64 + tid] = hn;
    }
    __syncthreads();

    // ---- fused Y for next iteration: Y = lnew @ Wih^T + gru_bih ----
    if (tid < 192) {
        const ull* lq = reinterpret_cast<const ull*>(lnew);
        const ull* wq = reinterpret_cast<const ull*>(g_wih_p);
        ull a = 0ull;
#pragma unroll 8
        for (int kp = 0; kp < 32; kp++)
            ffma2(a, lq[kp], wq[kp * 192 + tid]);
        g_Y[l * 192 + tid] = hsum2(a) + __ldg(&gbih[tid]);
    }
}

// ---------------- output copy ----------------
__global__ void copyout_kernel(float* __restrict__ out, int out_size)
{
    int i = blockIdx.x * blockDim.x + threadIdx.x;
    if (i >= out_size) return;
    if (i < Pn * Dn)
        out[i] = g_path_state[i];
    else if (i < Pn * Dn + Ln * Dn)
        out[i] = g_link_state[i - Pn * Dn];
}

// ---------------- launch ----------------
extern "C" void kernel_launch(void* const* d_in, const int* in_sizes, int n_in,
                              void* d_out, int out_size)
{
    const float* traffic  = (const float*)d_in[0];
    const float* capacity = (const float*)d_in[1];
    const int*   l2p      = (const int*)d_in[2];
    const int*   p2l      = (const int*)d_in[3];
    const float* pe_w1 = (const float*)d_in[4];
    const float* pe_b1 = (const float*)d_in[5];
    const float* pe_w2 = (const float*)d_in[6];
    const float* pe_b2 = (const float*)d_in[7];
    const float* le_w1 = (const float*)d_in[8];
    const float* le_b1 = (const float*)d_in[9];
    const float* le_w2 = (const float*)d_in[10];
    const float* le_b2 = (const float*)d_in[11];
    const float* gru_wih = (const float*)d_in[12];
    const float* gru_whh = (const float*)d_in[13];
    const float* gru_bih = (const float*)d_in[14];
    const float* gru_bhh = (const float*)d_in[15];
    const float* cell_wih = (const float*)d_in[16];
    const float* cell_whh = (const float*)d_in[17];
    const float* cell_bih = (const float*)d_in[18];
    const float* cell_bhh = (const float*)d_in[19];
    const float* am_w1 = (const float*)d_in[20];
    const float* am_b1 = (const float*)d_in[21];
    const float* am_w2 = (const float*)d_in[22];
    const float* am_b2 = (const float*)d_in[23];
    const float* am_w3 = (const float*)d_in[24];
    const float* am_b3 = (const float*)d_in[25];

    transpose_all_kernel<<<(32768 + 255) / 256, 256>>>(
        gru_wih, gru_whh, cell_wih, cell_whh, am_w1, am_w2, am_w3, pe_w2, le_w2);

    encoder_kernel<<<(Pn + 3) / 4, 256>>>(traffic, pe_w1, pe_b1, pe_b2, Pn, 0);
    encoder_kernel<<<(Ln + 3) / 4, 256>>>(capacity, le_w1, le_b1, le_b2, Ln, 1);

    linkgi_kernel<<<Ln, 192>>>(gru_bih);   // Y for iteration 0; later iters fused in link_kernel

    for (int it = 0; it < NITERS; it++) {
        gru_kernel<<<Pn / 32, 256>>>(l2p, gru_bhh);
        link_kernel<<<Ln, 256>>>((const int2*)p2l, am_b1, am_b2, am_b3,
                                 cell_bih, cell_bhh, gru_bih);
    }

    copyout_kernel<<<(out_size + 255) / 256, 256>>>((float*)d_out, out_size);
}

// round 14
// speedup vs baseline: 1.5599x; 1.1395x over previous
#include <cuda_runtime.h>
#include <math.h>

#define Pn   100000
#define Ln   20000
#define Tn   8
#define DEGn 48
#define Dn   64
#define NITERS 4

typedef unsigned long long ull;

// ---------------- device scratch (no allocation allowed) ----------------
__device__ float g_path_state[Pn * Dn];
__device__ float g_link_state[Ln * Dn];
__device__ __align__(16) float g_pss[Pn * (Tn + 1) * Dn];
__device__ __align__(16) float g_Y[Ln * 192];          // unpacked: Y[l][gate*64+d]

__device__ float g_gru_wihT[64 * 192];                 // scalar [k][j] (linkgi only)
__device__ __align__(16) float g_wih_p [32 * 384];     // k-pair packed gru Wih (link fused Y)
__device__ __align__(16) float g_whh_q [16 * 768];     // k-quad packed gru Whh: [kq][j][4]
__device__ __align__(16) float g_cwih_p[32 * 384];
__device__ __align__(16) float g_cwhh_p[32 * 384];
__device__ __align__(16) float g_am_w1p[128 * 256];
__device__ __align__(16) float g_am_w2p[64 * 256];
__device__ __align__(16) float g_am_w3p[64 * 128];
__device__ float g_pe_w2T[64 * 64];
__device__ float g_le_w2T[64 * 64];

// ---------------- helpers ----------------
__device__ __forceinline__ void ffma2(ull& d, ull a, ull b) { asm("fma.rn.f32x2 %0, %1, %2, %0;" : "+l"(d) : "l"(a), "l"(b)); }

__device__ __forceinline__ float hsum2(ull v) { float lo, hi; asm("mov.b64 {%0,%1}, %2;" : "=f"(lo), "=f"(hi) : "l"(v)); return lo + hi; }

__device__ __forceinline__ float sigf(float x) { return __fdividef(1.f, 1.f + __expf(-x)); }

__device__ __forceinline__ float tanhfast(float x) { return __fdividef(2.f, 1.f + __expf(-2.f * x)) - 1.f; }

// ---------------- weight transposes / packing ----------------
__global__ void transpose_all_kernel(
    const float* __restrict__ gwih, const float* __restrict__ gwhh,
    const float* __restrict__ cwih, const float* __restrict__ cwhh,
    const float* __restrict__ w1,   const float* __restrict__ w2,
    const float* __restrict__ w3,   const float* __restrict__ pw2,
    const float* __restrict__ lw2)
{
    int i = blockIdx.x * blockDim.x + threadIdx.x;
    if (i < 12288) {                // [192,64] sources; r = gate-row j, c = k
        int r = i >> 6, c = i & 63;
        int pk = (c >> 1) * 384 + r * 2 + (c & 1);
        g_gru_wihT[c * 192 + r] = gwih[i];
        g_wih_p [pk] = gwih[i];
        g_cwih_p[pk] = cwih[i];
        g_cwhh_p[pk] = cwhh[i];
        // k-quad interleave for gru Whh: [kq][j][k&3]
        g_whh_q[(c >> 2) * 768 + r * 4 + (c & 3)] = gwhh[i];
    }
    if (i < 32768) {
        int r = i >> 8, c = i & 255;
        g_am_w1p[(c >> 1) * 256 + r * 2 + (c & 1)] = w1[i];
    }
    if (i < 16384) {
        int r = i >> 7, c = i & 127;
        g_am_w2p[(c >> 1) * 256 + r * 2 + (c & 1)] = w2[i];
    }
    if (i < 8192) {
        int r = i >> 7, c = i & 127;
        g_am_w3p[(c >> 1) * 128 + r * 2 + (c & 1)] = w3[i];
    }
    if (i < 4096) {
        int r = i >> 6, c = i & 63;
        g_pe_w2T[c * 64 + r] = pw2[i];
        g_le_w2T[c * 64 + r] = lw2[i];
    }
}

// ---------------- encoders ----------------
__global__ __launch_bounds__(256) void encoder_kernel(
    const float* __restrict__ inp, const float* __restrict__ w1,
    const float* __restrict__ b1,  const float* __restrict__ b2,
    int N, int which)
{
    __shared__ float h1[4][64];
    int g = threadIdx.x >> 6, d = threadIdx.x & 63;
    int p = blockIdx.x * 4 + g;
    float v = 0.f;
    if (p < N) {
        float x = inp[p];
        v = fmaxf(fmaf(x, w1[d], b1[d]), 0.f);
    }
    h1[g][d] = v;
    __syncthreads();
    if (p < N) {
        const float* w2T = which ? g_le_w2T : g_pe_w2T;
        float acc = b2[d];
#pragma unroll
        for (int k = 0; k < 64; k++)
            acc = fmaf(h1[g][k], w2T[k * 64 + d], acc);
        float* out = which ? g_link_state : g_path_state;
        out[p * 64 + d] = fmaxf(acc, 0.f);
    }
}

// ---------------- Y = ls @ Wih^T + bih (iteration 0 only) ----------------
__global__ __launch_bounds__(192) void linkgi_kernel(const float* __restrict__ bih)
{
    __shared__ float ls[64];
    int l = blockIdx.x;
    int j = threadIdx.x;
    if (j < 64) ls[j] = g_link_state[l * 64 + j];
    __syncthreads();
    float acc = __ldg(&bih[j]);
#pragma unroll 8
    for (int k = 0; k < 64; k++)
        acc = fmaf(ls[k], g_gru_wihT[k * 192 + j], acc);
    g_Y[l * 192 + j] = acc;
}

// ---------------- path GRU over T=8 steps ----------------
// 256 threads = 4 groups x 64 dims, 8 paths/group. gh via FFMA2 with 128-bit
// h (LDS.128) and weight (LDG.128, k-quad layout) streams. gi gathered from Y
// in the epilogue. No occupancy clamp (avoid spills).
__global__ __launch_bounds__(256) void gru_kernel(
    const int* __restrict__ l2p, const float* __restrict__ bhh)
{
    __shared__ __align__(16) float h_sh[4][8][64];
    int g = threadIdx.x >> 6, d = threadIdx.x & 63;
    int pbase = blockIdx.x * 32 + g * 8;

#pragma unroll
    for (int r = 0; r < 8; r++) {
        int p = pbase + r;
        float h0 = g_path_state[p * 64 + d];
        h_sh[g][r][d] = h0;
        g_pss[p * 576 + d] = h0;
    }
    float b0h = __ldg(&bhh[d]);
    float b1h = __ldg(&bhh[64 + d]);
    float b2h = __ldg(&bhh[128 + d]);
    __syncthreads();

    const ulonglong2* wq = (const ulonglong2*)g_whh_q;   // (kq, j) at [kq*192 + j]

    for (int t = 0; t < Tn; t++) {
        ull a0[8], a1[8], a2[8];
#pragma unroll
        for (int r = 0; r < 8; r++) { a0[r] = 0ull; a1[r] = 0ull; a2[r] = 0ull; }

#pragma unroll 4
        for (int kq = 0; kq < 16; kq++) {
            ulonglong2 w0 = __ldg(&wq[kq * 192 + d]);
            ulonglong2 w1 = __ldg(&wq[kq * 192 + 64 + d]);
            ulonglong2 w2 = __ldg(&wq[kq * 192 + 128 + d]);
#pragma unroll
            for (int r = 0; r < 8; r++) {
                ulonglong2 hp = ((const ulonglong2*)&h_sh[g][r][0])[kq];
                ffma2(a0[r], hp.x, w0.x);
                ffma2(a0[r], hp.y, w0.y);
                ffma2(a1[r], hp.x, w1.x);
                ffma2(a1[r], hp.y, w1.y);
                ffma2(a2[r], hp.x, w2.x);
                ffma2(a2[r], hp.y, w2.y);
            }
        }
        __syncthreads();   // all h reads done before updates

        int lk[8];
#pragma unroll
        for (int r = 0; r < 8; r++)
            lk[r] = __ldg(&l2p[(pbase + r) * Tn + t]);

#pragma unroll
        for (int r = 0; r < 8; r++) {
            int lc = lk[r] < 0 ? 0 : lk[r];
            const float* yr = g_Y + lc * 192 + d;
            float gi0 = yr[0], gi1 = yr[64], gi2 = yr[128];
            float hold = h_sh[g][r][d];
            float gh0 = hsum2(a0[r]) + b0h;
            float gh1 = hsum2(a1[r]) + b1h;
            float gh2 = hsum2(a2[r]) + b2h;
            float rr = sigf(gi0 + gh0);
            float zz = sigf(gi1 + gh1);
            float nn = tanhfast(gi2 + rr * gh2);
            float hn = fmaf(zz, hold - nn, nn);
            int valid = lk[r] >= 0;
            h_sh[g][r][d] = valid ? hn : hold;
            g_pss[(pbase + r) * 576 + (t + 1) * 64 + d] = valid ? hn : 0.f;
        }
        __syncthreads();   // updates visible before next t's matmul
    }

#pragma unroll
    for (int r = 0; r < 8; r++)
        g_path_state[(pbase + r) * 64 + d] = h_sh[g][r][d];
}

// ---------------- link: gather + MLP + GRUCell + fused next-iter Y ----------------
__global__ __launch_bounds__(256) void link_kernel(
    const int2* __restrict__ p2l2,
    const float* __restrict__ am_b1, const float* __restrict__ am_b2,
    const float* __restrict__ am_b3,
    const float* __restrict__ cbih, const float* __restrict__ cbhh,
    const float* __restrict__ gbih)
{
    __shared__ __align__(8) float agg[256];
    __shared__ float red[4][3][64];
    __shared__ int   redc[4];
    __shared__ __align__(8) float h1[128];
    __shared__ __align__(8) float h2[128];
    __shared__ __align__(8) float pa[64];
    __shared__ __align__(8) float hrow[64];
    __shared__ __align__(8) float lnew[64];
    __shared__ float part[2][128];
    __shared__ float part4[4][64];
    __shared__ float gis[192], ghs[192];

    int l = blockIdx.x;
    int tid = threadIdx.x;
    int q = tid >> 6, d = tid & 63;
    int hf = tid >> 7, j = tid & 127;

    if (tid < 64) hrow[tid] = g_link_state[l * 64 + tid];

    float mn = INFINITY, mx = -INFINITY, sm = 0.f;
    int cnt = 0;
#pragma unroll
    for (int e = q; e < DEGn; e += 4) {
        int2 pp = __ldg(&p2l2[l * DEGn + e]);
        if (pp.x >= 0) {
            float v = g_pss[pp.x * 576 + pp.y * 64 + d];
            mn = fminf(mn, v); mx = fmaxf(mx, v); sm += v; cnt++;
        }
    }
    red[q][0][d] = mn; red[q][1][d] = mx; red[q][2][d] = sm;
    if (d == 0) redc[q] = cnt;
    __syncthreads();

    if (tid < 64) {
        float amn = red[0][0][d], amx = red[0][1][d], s = red[0][2][d];
#pragma unroll
        for (int q2 = 1; q2 < 4; q2++) {
            amn = fminf(amn, red[q2][0][d]);
            amx = fmaxf(amx, red[q2][1][d]);
            s += red[q2][2][d];
        }
        int c = redc[0] + redc[1] + redc[2] + redc[3];
        float fc = (float)(c < 1 ? 1 : c);
        agg[d] = amn; agg[64 + d] = amx; agg[128 + d] = s; agg[192 + d] = __fdividef(s, fc);
    }
    __syncthreads();

    {
        const ull* aggq = (const ull*)agg;
        const ull* wq = (const ull*)g_am_w1p;
        ull acc = 0ull;
#pragma unroll 8
        for (int kp = hf * 64; kp < hf * 64 + 64; kp++)
            ffma2(acc, aggq[kp], wq[kp * 128 + j]);
        part[hf][j] = hsum2(acc);
    }
    __syncthreads();
    if (tid < 128)
        h1[tid] = fmaxf(part[0][tid] + part[1][tid] + __ldg(&am_b1[tid]), 0.f);
    __syncthreads();

    {
        const ull* h1q = (const ull*)h1;
        const ull* wq = (const ull*)g_am_w2p;
        ull acc = 0ull;
#pragma unroll 8
        for (int kp = hf * 32; kp < hf * 32 + 32; kp++)
            ffma2(acc, h1q[kp], wq[kp * 128 + j]);
        part[hf][j] = hsum2(acc);
    }
    __syncthreads();
    if (tid < 128)
        h2[tid] = fmaxf(part[0][tid] + part[1][tid] + __ldg(&am_b2[tid]), 0.f);
    __syncthreads();

    {
        const ull* h2q = (const ull*)h2;
        const ull* wq = (const ull*)g_am_w3p;
        ull acc = 0ull;
#pragma unroll 8
        for (int kp = q * 16; kp < q * 16 + 16; kp++)
            ffma2(acc, h2q[kp], wq[kp * 64 + d]);
        part4[q][d] = hsum2(acc);
    }
    __syncthreads();
    if (tid < 64)
        pa[tid] = fmaxf(part4[0][tid] + part4[1][tid] + part4[2][tid] + part4[3][tid]
                        + __ldg(&am_b3[tid]), 0.f);
    __syncthreads();

    if (tid < 192) {
        const ull* paq = (const ull*)pa;
        const ull* hq  = (const ull*)hrow;
        const ull* wiq = (const ull*)g_cwih_p;
        const ull* whq = (const ull*)g_cwhh_p;
        ull ai = 0ull, ah = 0ull;
#pragma unroll 8
        for (int kp = 0; kp < 32; kp++) {
            ffma2(ai, paq[kp], wiq[kp * 192 + tid]);
            ffma2(ah, hq[kp],  whq[kp * 192 + tid]);
        }
        gis[tid] = hsum2(ai) + __ldg(&cbih[tid]);
        ghs[tid] = hsum2(ah) + __ldg(&cbhh[tid]);
    }
    __syncthreads();
    if (tid < 64) {
        float hold = hrow[tid];
        float rr = sigf(gis[tid] + ghs[tid]);
        float zz = sigf(gis[64 + tid] + ghs[64 + tid]);
        float nn = tanhfast(gis[128 + tid] + rr * ghs[128 + tid]);
        float hn = fmaf(zz, hold - nn, nn);
        lnew[tid] = hn;
        g_link_state[l * 64 + tid] = hn;
    }
    __syncthreads();

    // fused Y (unpacked [gate*64+d] = [j]) for next iteration
    if (tid < 192) {
        const ull* lq = (const ull*)lnew;
        const ull* wq = (const ull*)g_wih_p;
        ull a = 0ull;
#pragma unroll 8
        for (int kp = 0; kp < 32; kp++)
            ffma2(a, lq[kp], wq[kp * 192 + tid]);
        g_Y[l * 192 + tid] = hsum2(a) + __ldg(&gbih[tid]);
    }
}

// ---------------- output copy ----------------
__global__ void copyout_kernel(float* __restrict__ out, int out_size)
{
    int i = blockIdx.x * blockDim.x + threadIdx.x;
    if (i >= out_size) return;
    if (i < Pn * Dn)
        out[i] = g_path_state[i];
    else if (i < Pn * Dn + Ln * Dn)
        out[i] = g_link_state[i - Pn * Dn];
}

// ---------------- launch ----------------
extern "C" void kernel_launch(void* const* d_in, const int* in_sizes, int n_in,
                              void* d_out, int out_size)
{
    const float* traffic  = (const float*)d_in[0];
    const float* capacity = (const float*)d_in[1];
    const int*   l2p      = (const int*)d_in[2];
    const int*   p2l      = (const int*)d_in[3];
    const float* pe_w1 = (const float*)d_in[4];
    const float* pe_b1 = (const float*)d_in[5];
    const float* pe_w2 = (const float*)d_in[6];
    const float* pe_b2 = (const float*)d_in[7];
    const float* le_w1 = (const float*)d_in[8];
    const float* le_b1 = (const float*)d_in[9];
    const float* le_w2 = (const float*)d_in[10];
    const float* le_b2 = (const float*)d_in[11];
    const float* gru_wih = (const float*)d_in[12];
    const float* gru_whh = (const float*)d_in[13];
    const float* gru_bih = (const float*)d_in[14];
    const float* gru_bhh = (const float*)d_in[15];
    const float* cell_wih = (const float*)d_in[16];
    const float* cell_whh = (const float*)d_in[17];
    const float* cell_bih = (const float*)d_in[18];
    const float* cell_bhh = (const float*)d_in[19];
    const float* am_w1 = (const float*)d_in[20];
    const float* am_b1 = (const float*)d_in[21];
    const float* am_w2 = (const float*)d_in[22];
    const float* am_b2 = (const float*)d_in[23];
    const float* am_w3 = (const float*)d_in[24];
    const float* am_b3 = (const float*)d_in[25];

    transpose_all_kernel<<<(32768 + 255) / 256, 256>>>(
        gru_wih, gru_whh, cell_wih, cell_whh, am_w1, am_w2, am_w3, pe_w2, le_w2);

    encoder_kernel<<<(Pn + 3) / 4, 256>>>(traffic, pe_w1, pe_b1, pe_b2, Pn, 0);
    encoder_kernel<<<(Ln + 3) / 4, 256>>>(capacity, le_w1, le_b1, le_b2, Ln, 1);

    linkgi_kernel<<<Ln, 192>>>(gru_bih);

    for (int it = 0; it < NITERS; it++) {
        gru_kernel<<<Pn / 32, 256>>>(l2p, gru_bhh);
        link_kernel<<<Ln, 256>>>((const int2*)p2l, am_b1, am_b2, am_b3,
                                 cell_bih, cell_bhh, gru_bih);
    }

    copyout_kernel<<<(out_size + 255) / 256, 256>>>((float*)d_out, out_size);
}